// round 5
// baseline (speedup 1.0000x reference)
#include <cuda_runtime.h>

#define TCOLS 4096
#define BROWS 4096
#define NT 128                 // 4 warps/block, 1 row per warp
#define ROWS_PER_BLK (NT / 32)
#define GRID (BROWS / ROWS_PER_BLK)
#define FULL 0xffffffffu

__device__ float    g_partials[BROWS];
__device__ unsigned g_done;    // zero-init; reset by last block each launch

__device__ __forceinline__ float warp_sum(float v) {
    #pragma unroll
    for (int o = 16; o; o >>= 1) v += __shfl_xor_sync(FULL, v, o);
    return v;
}

// ---- Pass 1 over one mask-word (8 chunks of 128 floats). Chunk c: lane owns
// elements c*128 + 4*lane .. +3. Batched loads give MLP=9 per word. ----
template <int WORD>
__device__ __forceinline__ void pass1_word(const float4* __restrict__ g, int lane,
                                           float& carry, float& psum, float& vsum,
                                           unsigned& pkm, unsigned& vym) {
    float4 v[9];
    #pragma unroll
    for (int j = 0; j < 8; j++) v[j] = g[(WORD * 8 + j) * 32 + lane];
    v[8] = (WORD < 3) ? g[(WORD * 8 + 8) * 32 + lane] : v[7];

    if (WORD == 0) carry = __shfl_sync(FULL, v[0].x, 0);  // row start: d0 = 0

    #pragma unroll
    for (int j = 0; j < 8; j++) {
        const int c = WORD * 8 + j;
        float lead = __shfl_sync(FULL, v[j + 1].x, 0);
        float lv = __shfl_up_sync(FULL, v[j].w, 1);
        if (lane == 0) lv = carry;
        float rv = __shfl_down_sync(FULL, v[j].x, 1);
        if (lane == 31) rv = (c == 31) ? v[j].w : lead;  // row end: d4 = 0

        float e0 = v[j].x, e1 = v[j].y, e2 = v[j].z, e3 = v[j].w;
        float d0 = e0 - lv, d1 = e1 - e0, d2 = e2 - e1, d3 = e3 - e2, d4 = rv - e3;
        float ee[4] = {e0, e1, e2, e3};
        float dd[5] = {d0, d1, d2, d3, d4};
        #pragma unroll
        for (int k = 0; k < 4; k++) {
            bool pk = fminf(dd[k], -dd[k + 1]) > 0.f;   // dl>0 && dr<0
            bool vy = fmaxf(dd[k], -dd[k + 1]) < 0.f;   // dl<0 && dr>0
            if (pk) { psum += ee[k]; pkm |= 1u << (j * 4 + k); }
            if (vy) { vsum += ee[k]; vym |= 1u << (j * 4 + k); }
        }
        carry = __shfl_sync(FULL, v[j].w, 31);
    }
}

// ---- Pass 2 over one mask-word: reload (L1/L2 hits) and apply thresholds. ----
template <int WORD>
__device__ __forceinline__ void pass2_word(const float4* __restrict__ g, int lane,
                                           unsigned pkm, unsigned vym,
                                           float pm, float vm,
                                           float& ssbp, int& csbp,
                                           float& sdbp, int& cdbp) {
    float4 v[8];
    #pragma unroll
    for (int j = 0; j < 8; j++) v[j] = g[(WORD * 8 + j) * 32 + lane];

    #pragma unroll
    for (int j = 0; j < 8; j++) {
        float ee[4] = {v[j].x, v[j].y, v[j].z, v[j].w};
        #pragma unroll
        for (int k = 0; k < 4; k++) {
            const unsigned bit = 1u << (j * 4 + k);
            if ((pkm & bit) && ee[k] >= pm) { ssbp += ee[k]; csbp++; }
            if ((vym & bit) && ee[k] <= vm) { sdbp += ee[k]; cdbp++; }
        }
    }
}

__device__ __forceinline__ void process_array(const float* __restrict__ row,
                                              int lane, float& sbp, float& dbp) {
    const float4* g = (const float4*)row;

    float carry = 0.f, psum = 0.f, vsum = 0.f;
    unsigned pk0 = 0, pk1 = 0, pk2 = 0, pk3 = 0;
    unsigned vy0 = 0, vy1 = 0, vy2 = 0, vy3 = 0;
    pass1_word<0>(g, lane, carry, psum, vsum, pk0, vy0);
    pass1_word<1>(g, lane, carry, psum, vsum, pk1, vy1);
    pass1_word<2>(g, lane, carry, psum, vsum, pk2, vy2);
    pass1_word<3>(g, lane, carry, psum, vsum, pk3, vy3);

    float ps = warp_sum(psum);
    float vs = warp_sum(vsum);
    int pc = __reduce_add_sync(FULL, __popc(pk0) + __popc(pk1) + __popc(pk2) + __popc(pk3));
    int vc = __reduce_add_sync(FULL, __popc(vy0) + __popc(vy1) + __popc(vy2) + __popc(vy3));
    const float pm = ps / (float)pc;
    const float vm = vs / (float)vc;

    float ssbp = 0.f, sdbp = 0.f;
    int   csbp = 0,   cdbp = 0;
    pass2_word<0>(g, lane, pk0, vy0, pm, vm, ssbp, csbp, sdbp, cdbp);
    pass2_word<1>(g, lane, pk1, vy1, pm, vm, ssbp, csbp, sdbp, cdbp);
    pass2_word<2>(g, lane, pk2, vy2, pm, vm, ssbp, csbp, sdbp, cdbp);
    pass2_word<3>(g, lane, pk3, vy3, pm, vm, ssbp, csbp, sdbp, cdbp);

    sbp = warp_sum(ssbp) / (float)__reduce_add_sync(FULL, csbp);
    dbp = warp_sum(sdbp) / (float)__reduce_add_sync(FULL, cdbp);
}

__global__ __launch_bounds__(NT)
void pv_warprow_kernel(const float* __restrict__ preds,
                       const float* __restrict__ labels,
                       float* __restrict__ out) {
    __shared__ float red[ROWS_PER_BLK];
    __shared__ bool  amLast;

    const int lane = threadIdx.x & 31;
    const int wid  = threadIdx.x >> 5;
    const int row  = blockIdx.x * ROWS_PER_BLK + wid;

    float sbp_p, dbp_p, sbp_l, dbp_l;
    process_array(preds  + (size_t)row * TCOLS, lane, sbp_p, dbp_p);
    process_array(labels + (size_t)row * TCOLS, lane, sbp_l, dbp_l);

    if (lane == 0) {
        float d0 = sbp_p - sbp_l;
        float d1 = dbp_p - dbp_l;
        g_partials[row] = d0 * d0 + d1 * d1;
    }
    __syncthreads();
    if (threadIdx.x == 0) {
        __threadfence();
        unsigned c = atomicAdd(&g_done, 1u);
        amLast = (c == (unsigned)(gridDim.x - 1));
    }
    __syncthreads();

    // ---- Last block: reduce all per-row partials, write scalar, reset. ----
    if (amLast) {
        float v = 0.f;
        #pragma unroll
        for (int q = 0; q < BROWS / NT; q++) v += g_partials[threadIdx.x + q * NT];
        v = warp_sum(v);
        if (lane == 0) red[wid] = v;
        __syncthreads();
        if (threadIdx.x == 0) {
            float t = 0.f;
            #pragma unroll
            for (int w = 0; w < ROWS_PER_BLK; w++) t += red[w];
            out[0] = t / (float)(BROWS * 2);
            g_done = 0;
        }
    }
}

extern "C" void kernel_launch(void* const* d_in, const int* in_sizes, int n_in,
                              void* d_out, int out_size) {
    const float* preds  = (const float*)d_in[0];
    const float* labels = (const float*)d_in[1];
    pv_warprow_kernel<<<GRID, NT>>>(preds, labels, (float*)d_out);
}

// round 6
// speedup vs baseline: 1.1594x; 1.1594x over previous
#include <cuda_runtime.h>

#define TCOLS 4096
#define BROWS 4096
#define NT 256
#define NW 8            // warps per block
#define WELEM 512       // elements per warp (4 float4 groups per lane)
#define FULL 0xffffffffu

__device__ float    g_partials[BROWS];
__device__ unsigned g_done;   // zero-init; reset by last block each launch

__device__ __forceinline__ float warp_sum(float v) {
    #pragma unroll
    for (int o = 16; o; o >>= 1) v += __shfl_xor_sync(FULL, v, o);
    return v;
}

// Block-reduce 4 float sums + 4 int counts; broadcast into out[8] (counts as float).
__device__ __forceinline__ void block_reduce8(float s[4], int c[4],
                                              float out[8], float* redf,
                                              int lane, int wid) {
    #pragma unroll
    for (int j = 0; j < 4; j++) s[j] = warp_sum(s[j]);
    #pragma unroll
    for (int j = 0; j < 4; j++) c[j] = __reduce_add_sync(FULL, c[j]);
    if (lane == 0) {
        #pragma unroll
        for (int j = 0; j < 4; j++) {
            redf[j * NW + wid]       = s[j];
            redf[(4 + j) * NW + wid] = (float)c[j];
        }
    }
    __syncthreads();
    // 8 warps each reduce one value over NW=8 partials
    float v = (lane < NW) ? redf[wid * NW + lane] : 0.f;
    v += __shfl_xor_sync(FULL, v, 4);
    v += __shfl_xor_sync(FULL, v, 2);
    v += __shfl_xor_sync(FULL, v, 1);
    if (lane == 0) redf[64 + wid] = v;
    __syncthreads();
    #pragma unroll
    for (int j = 0; j < 8; j++) out[j] = redf[64 + j];
    __syncthreads();
}

// Peak/valley over one float4 (4 centers) given left/right neighbor values.
__device__ __forceinline__ void pv_group(float4 v, float lv, float rv, int shift,
                                         float& psum, float& vsum,
                                         unsigned& pkm, unsigned& vym) {
    float e[4] = {v.x, v.y, v.z, v.w};
    float d[5];
    d[0] = v.x - lv;
    d[1] = v.y - v.x;
    d[2] = v.z - v.y;
    d[3] = v.w - v.z;
    d[4] = rv - v.w;
    #pragma unroll
    for (int k = 0; k < 4; k++) {
        bool pk = (d[k] > 0.f) && (d[k + 1] < 0.f);
        bool vy = (d[k] < 0.f) && (d[k + 1] > 0.f);
        if (pk) { psum += e[k]; pkm |= 1u << (shift + k); }
        if (vy) { vsum += e[k]; vym |= 1u << (shift + k); }
    }
}

__global__ __launch_bounds__(NT, 5)
void pv_fused_kernel(const float* __restrict__ preds,
                     const float* __restrict__ labels,
                     float* __restrict__ out) {
    __shared__ float red[72];
    __shared__ bool  amLast;

    const int row  = blockIdx.x;
    const int tid  = threadIdx.x;
    const int lane = tid & 31;
    const int wid  = tid >> 5;
    const int wb   = wid * WELEM;

    const float* rp = preds  + (size_t)row * TCOLS;
    const float* rl = labels + (size_t)row * TCOLS;
    const float4* gp = (const float4*)(rp + wb);
    const float4* gl = (const float4*)(rl + wb);

    // Row/warp edge neighbor values; NaN at row ends disables those centers.
    const float NANF = __int_as_float(0x7fffffff);
    float wlp = NANF, wll = NANF, wrp = NANF, wrl = NANF;
    if (lane == 0 && wb > 0)              { wlp = rp[wb - 1];     wll = rl[wb - 1]; }
    if (lane == 31 && wb + WELEM < TCOLS) { wrp = rp[wb + WELEM]; wrl = rl[wb + WELEM]; }

    // ---- Pass 1: streamed, depth-2 pipelined over 4 groups ----
    float psum_p = 0.f, vsum_p = 0.f, psum_l = 0.f, vsum_l = 0.f;
    unsigned pkm_p = 0, vym_p = 0, pkm_l = 0, vym_l = 0;

    float4 cp = gp[lane];
    float4 cl = gl[lane];
    float carry_p = wlp, carry_l = wll;   // consumed by lane 0 only

    #pragma unroll
    for (int g = 0; g < 4; g++) {
        float4 np, nl;
        if (g < 3) { np = gp[(g + 1) * 32 + lane]; nl = gl[(g + 1) * 32 + lane]; }

        float lead_p = (g < 3) ? __shfl_sync(FULL, np.x, 0) : wrp;
        float lead_l = (g < 3) ? __shfl_sync(FULL, nl.x, 0) : wrl;

        float lv = __shfl_up_sync(FULL, cp.w, 1);
        if (lane == 0) lv = carry_p;
        float rv = __shfl_down_sync(FULL, cp.x, 1);
        if (lane == 31) rv = lead_p;
        pv_group(cp, lv, rv, g * 4, psum_p, vsum_p, pkm_p, vym_p);
        carry_p = __shfl_sync(FULL, cp.w, 31);

        lv = __shfl_up_sync(FULL, cl.w, 1);
        if (lane == 0) lv = carry_l;
        rv = __shfl_down_sync(FULL, cl.x, 1);
        if (lane == 31) rv = lead_l;
        pv_group(cl, lv, rv, g * 4, psum_l, vsum_l, pkm_l, vym_l);
        carry_l = __shfl_sync(FULL, cl.w, 31);

        cp = np; cl = nl;
    }

    {
        float s1[4] = {psum_p, vsum_p, psum_l, vsum_l};
        int   c1[4] = {__popc(pkm_p), __popc(vym_p), __popc(pkm_l), __popc(vym_l)};
        float o1[8];
        block_reduce8(s1, c1, o1, red, lane, wid);

        const float pmean_p = o1[0] / o1[4];
        const float vmean_p = o1[1] / o1[5];
        const float pmean_l = o1[2] / o1[6];
        const float vmean_l = o1[3] / o1[7];

        // ---- Pass 2: reload (L1-hot) and apply thresholds; counts via popc ----
        float s0 = 0.f, s1f = 0.f, s2 = 0.f, s3 = 0.f;
        unsigned m0 = 0, m1 = 0, m2 = 0, m3 = 0;

        #pragma unroll
        for (int g = 0; g < 4; g++) {
            float4 a = gp[g * 32 + lane];
            float4 b = gl[g * 32 + lane];
            float ea[4] = {a.x, a.y, a.z, a.w};
            float eb[4] = {b.x, b.y, b.z, b.w};
            #pragma unroll
            for (int k = 0; k < 4; k++) {
                const int idx = g * 4 + k;
                const unsigned bit = 1u << idx;
                if ((pkm_p & bit) && ea[k] >= pmean_p) { s0 += ea[k]; m0 |= bit; }
                if ((vym_p & bit) && ea[k] <= vmean_p) { s1f += ea[k]; m1 |= bit; }
                if ((pkm_l & bit) && eb[k] >= pmean_l) { s2 += eb[k]; m2 |= bit; }
                if ((vym_l & bit) && eb[k] <= vmean_l) { s3 += eb[k]; m3 |= bit; }
            }
        }

        float s2v[4] = {s0, s1f, s2, s3};
        int   c2v[4] = {__popc(m0), __popc(m1), __popc(m2), __popc(m3)};
        float o2[8];
        block_reduce8(s2v, c2v, o2, red, lane, wid);

        if (tid == 0) {
            float sbp_p = o2[0] / o2[4];
            float dbp_p = o2[1] / o2[5];
            float sbp_l = o2[2] / o2[6];
            float dbp_l = o2[3] / o2[7];
            float d0 = sbp_p - sbp_l;
            float d1 = dbp_p - dbp_l;
            g_partials[row] = d0 * d0 + d1 * d1;
            __threadfence();
            unsigned cdone = atomicAdd(&g_done, 1u);
            amLast = (cdone == (unsigned)(gridDim.x - 1));
        }
    }
    __syncthreads();

    // ---- Last block: reduce per-row partials, write scalar, reset counter ----
    if (amLast) {
        float v = 0.f;
        #pragma unroll
        for (int q = 0; q < BROWS / NT; q++) v += g_partials[tid + q * NT];
        v = warp_sum(v);
        if (lane == 0) red[wid] = v;
        __syncthreads();
        if (tid == 0) {
            float t = 0.f;
            #pragma unroll
            for (int w = 0; w < NW; w++) t += red[w];
            out[0] = t / (float)(BROWS * 2);
            g_done = 0;
        }
    }
}

extern "C" void kernel_launch(void* const* d_in, const int* in_sizes, int n_in,
                              void* d_out, int out_size) {
    const float* preds  = (const float*)d_in[0];
    const float* labels = (const float*)d_in[1];
    pv_fused_kernel<<<BROWS, NT>>>(preds, labels, (float*)d_out);
}